// round 16
// baseline (speedup 1.0000x reference)
#include <cuda_runtime.h>
#include <cuda_fp16.h>
#include <cstdint>

// Problem constants (fixed by the dataset)
#define NXc   1024          // input features (K)
#define NFc   4096          // output features (N)
#define BITSc 8             // bit planes
#define Gc    128           // NX/8 packed groups
#define Mc    4096          // tokens (2*2048)

#define BM 128
#define BN 128
#define KC 16               // k-chunks of 64
#define NSTEP (KC * 4)      // 64 flat (chunk, ks) steps
#define NT 1024             // tiles (32 x 32)

#define GRID_F 296          // 2 per SM on a 148-SM die; all co-resident
#define NTHREADS (GRID_F * 256)

#define DECODE_ITEMS (NFc * (Gc / 4))     // 131072
#define REPACK_ITEMS (Mc * NXc / 8)       // 524288

// Fragment-major fp16 tiles (uint32 = half2), 16KB each:
//   A tile: [mt(8)][ks(4)][lane(32)][4 u32]
//   B tile: [ntp(8)][ks(4)][lane(32)][4 u32]  (pair-interleaved: two n8 frags)
#define TILE_U32   4096

__device__ uint32_t g_Xt[(size_t)Mc * NXc / 2];   // [m_blk(32)][kc(16)][TILE]
__device__ uint32_t g_Wt[(size_t)NFc * NXc / 2];  // [n_blk(32)][kc(16)][TILE]
__device__ unsigned g_ctr;                         // monotone barrier counter

// ---------------------------------------------------------------------------
__device__ __forceinline__ uint32_t pack_h2(float lo, float hi) {
    __half2 h = __floats2half2_rn(lo, hi);   // lo -> low 16 bits
    return *reinterpret_cast<uint32_t*>(&h);
}
__device__ __forceinline__ void mma_f16(float* d, const uint32_t* a, const uint32_t* b) {
    asm volatile(
        "mma.sync.aligned.m16n8k16.row.col.f32.f16.f16.f32 "
        "{%0,%1,%2,%3}, {%4,%5,%6,%7}, {%8,%9}, {%0,%1,%2,%3};"
        : "+f"(d[0]), "+f"(d[1]), "+f"(d[2]), "+f"(d[3])
        : "r"(a[0]), "r"(a[1]), "r"(a[2]), "r"(a[3]), "r"(b[0]), "r"(b[1]));
}
// exact sign-inject: s if bit (7-j) of the ORIGINAL byte is 1, else -s.
// nb is the pre-complemented byte (set bit => positive after XOR trick).
__device__ __forceinline__ float sgn_inj(float s, uint32_t nb, int j) {
    uint32_t u = __float_as_uint(s) ^ ((nb << (24 + j)) & 0x80000000u);
    return __uint_as_float(u);
}

// ---------------------------------------------------------------------------
// Prep work items (same math + layouts as the verified R15 prep kernel)
// ---------------------------------------------------------------------------
__device__ __forceinline__ void decode_item(
    int item, const int* __restrict__ binary, const float* __restrict__ scale) {
    int f = item >> 5;          // output feature
    int q = item & 31;          // quad-group index: groups 4q..4q+3

    float w[32];
#pragma unroll
    for (int j = 0; j < 32; j++) w[j] = 0.0f;

#pragma unroll
    for (int k = 0; k < BITSc; k++) {
        int4 bb = *reinterpret_cast<const int4*>(
            binary + (size_t)(k * NFc + f) * Gc + 4 * q);
        float s = __ldg(scale + k * NFc + f);
        uint32_t n0 = ~(uint32_t)bb.x;
        uint32_t n1 = ~(uint32_t)bb.y;
        uint32_t n2 = ~(uint32_t)bb.z;
        uint32_t n3 = ~(uint32_t)bb.w;
#pragma unroll
        for (int j = 0; j < 8; j++) {
            w[j]      += sgn_inj(s, n0, j);
            w[8 + j]  += sgn_inj(s, n1, j);
            w[16 + j] += sgn_inj(s, n2, j);
            w[24 + j] += sgn_inj(s, n3, j);
        }
    }

    int n_blk = f >> 7;
    int nt    = (f & 127) >> 3;    // 0..15
    int ntp   = nt >> 1;           // pair index 0..7
    int half  = nt & 1;            // low/high half of the uint4
    int col   = f & 7;
    int kc    = q >> 1;            // k-chunk (BK=64)

    uint32_t* tile = g_Wt + (size_t)(n_blk * KC + kc) * TILE_U32;
#pragma unroll
    for (int t = 0; t < 2; t++) {
        int ks = (q & 1) * 2 + t;      // k16-step within chunk
        const float* wt = w + 16 * t;
#pragma unroll
        for (int c = 0; c < 4; c++) {
            uint2 v;
            v.x = pack_h2(wt[2 * c], wt[2 * c + 1]);          // reg b0
            v.y = pack_h2(wt[8 + 2 * c], wt[9 + 2 * c]);      // reg b1
            *reinterpret_cast<uint2*>(
                tile + ((ntp * 4 + ks) * 32 + col * 4 + c) * 4 + half * 2) = v;
        }
    }
}

__device__ __forceinline__ void repack_item(int item, const float* __restrict__ x) {
    int lane = item & 31;
    int ks   = (item >> 5) & 3;
    int mt   = (item >> 7) & 7;
    int kc   = (item >> 10) & (KC - 1);
    int mblk = item >> 14;

    int row = mblk * BM + mt * 16 + (lane >> 2);
    int k0  = kc * 64 + ks * 16 + (lane & 3) * 2;

    const float* r0 = x + (size_t)row * NXc;
    const float* r1 = r0 + 8 * NXc;

    float2 p00 = *reinterpret_cast<const float2*>(r0 + k0);
    float2 p10 = *reinterpret_cast<const float2*>(r1 + k0);
    float2 p01 = *reinterpret_cast<const float2*>(r0 + k0 + 8);
    float2 p11 = *reinterpret_cast<const float2*>(r1 + k0 + 8);

    uint4 v;
    v.x = pack_h2(p00.x, p00.y);
    v.y = pack_h2(p10.x, p10.y);
    v.z = pack_h2(p01.x, p01.y);
    v.w = pack_h2(p11.x, p11.y);

    uint32_t* tile = g_Xt + (size_t)(mblk * KC + kc) * TILE_U32;
    *reinterpret_cast<uint4*>(tile + ((mt * 4 + ks) * 32 + lane) * 4) = v;
}

// ---------------------------------------------------------------------------
// Fused kernel: prep (grid-stride) -> software grid barrier -> persistent
// barrier-free fp16 mma.sync GEMM (R14 inner loop, frozen).
// 296 CTAs x 256 threads, all co-resident (2/SM guaranteed by launch bounds),
// so the spin barrier cannot deadlock. The barrier counter is monotone:
// each launch's target is the next multiple of GRID_F, so no reset is needed
// across graph replays.
// ---------------------------------------------------------------------------
__global__ void __launch_bounds__(256, 2)
fused_kernel(const int* __restrict__ binary, const float* __restrict__ scale,
             const float* __restrict__ x, const float* __restrict__ bias,
             float* __restrict__ out) {
    const int tid  = threadIdx.x;
    const int bid  = blockIdx.x;
    const int gt   = bid * 256 + tid;

    // ---------------- phase 1: prep ----------------
    for (int i = gt; i < DECODE_ITEMS; i += NTHREADS)
        decode_item(i, binary, scale);
    for (int i = gt; i < REPACK_ITEMS; i += NTHREADS)
        repack_item(i, x);

    // ---------------- grid barrier ----------------
    __threadfence();
    __syncthreads();
    if (tid == 0) {
        unsigned my = atomicAdd(&g_ctr, 1u);               // old value
        unsigned target = (my / GRID_F + 1u) * GRID_F;     // this launch's release
        unsigned v;
        do {
            asm volatile("ld.acquire.gpu.u32 %0, [%1];"
                         : "=r"(v) : "l"(&g_ctr));
        } while (v < target);
    }
    __syncthreads();

    // ---------------- phase 2: persistent GEMM ----------------
    const int lane = tid & 31;
    const int wid  = tid >> 5;
    const int wm   = wid >> 2;      // 0..1
    const int wn   = wid & 3;       // 0..3

    for (int t = bid; t < NT; t += GRID_F) {
        const int m_blk = t >> 5;
        const int n_blk = t & 31;

        // warp-private fragment stream bases (u32 units)
        const uint32_t* Aw = g_Xt + (size_t)m_blk * KC * TILE_U32
                           + ((wm * 4) * 4 * 32 + lane) * 4;
        const uint32_t* Bw = g_Wt + (size_t)n_blk * KC * TILE_U32
                           + (((wn * 2) * 4) * 32 + lane) * 4;

        float acc[4][4][4];
#pragma unroll
        for (int i = 0; i < 4; i++)
#pragma unroll
            for (int j = 0; j < 4; j++)
#pragma unroll
                for (int r = 0; r < 4; r++) acc[i][j][r] = 0.0f;

        uint32_t a[2][4][4], b[2][4][2];

        // preload step 0
#pragma unroll
        for (int i = 0; i < 4; i++) {
            uint4 v = __ldg(reinterpret_cast<const uint4*>(Aw + i * 512));
            a[0][i][0] = v.x; a[0][i][1] = v.y; a[0][i][2] = v.z; a[0][i][3] = v.w;
        }
#pragma unroll
        for (int jp = 0; jp < 2; jp++) {
            uint4 v = __ldg(reinterpret_cast<const uint4*>(Bw + jp * 512));
            b[0][2 * jp][0]     = v.x; b[0][2 * jp][1]     = v.y;
            b[0][2 * jp + 1][0] = v.z; b[0][2 * jp + 1][1] = v.w;
        }

#pragma unroll 4
        for (int s = 0; s < NSTEP; s++) {
            const int cur = s & 1, nxt = cur ^ 1;

            if (s < NSTEP - 1) {
                const int sn  = s + 1;
                const int off = (sn >> 2) * 4096 + (sn & 3) * 128;
#pragma unroll
                for (int i = 0; i < 4; i++) {
                    uint4 v = __ldg(reinterpret_cast<const uint4*>(Aw + off + i * 512));
                    a[nxt][i][0] = v.x; a[nxt][i][1] = v.y;
                    a[nxt][i][2] = v.z; a[nxt][i][3] = v.w;
                }
#pragma unroll
                for (int jp = 0; jp < 2; jp++) {
                    uint4 v = __ldg(reinterpret_cast<const uint4*>(Bw + off + jp * 512));
                    b[nxt][2 * jp][0]     = v.x; b[nxt][2 * jp][1]     = v.y;
                    b[nxt][2 * jp + 1][0] = v.z; b[nxt][2 * jp + 1][1] = v.w;
                }
            }

#pragma unroll
            for (int i = 0; i < 4; i++)
#pragma unroll
                for (int j = 0; j < 4; j++)
                    mma_f16(acc[i][j], a[cur][i], b[cur][j]);
        }

        // epilogue: c0,c1 at (row, col/col+1); c2,c3 at (row+8, ·)
        const int row0 = m_blk * BM + wm * 64 + (lane >> 2);
        const int col0 = n_blk * BN + wn * 32 + (lane & 3) * 2;
#pragma unroll
        for (int j = 0; j < 4; j++) {
            const int n = col0 + j * 8;
            const float2 bv = *reinterpret_cast<const float2*>(bias + n);
#pragma unroll
            for (int i = 0; i < 4; i++) {
                const int m = row0 + i * 16;
                float2 v0, v1;
                v0.x = acc[i][j][0] + bv.x;
                v0.y = acc[i][j][1] + bv.y;
                v1.x = acc[i][j][2] + bv.x;
                v1.y = acc[i][j][3] + bv.y;
                *reinterpret_cast<float2*>(out + (size_t)m * NFc + n)       = v0;
                *reinterpret_cast<float2*>(out + (size_t)(m + 8) * NFc + n) = v1;
            }
        }
    }
}

// ---------------------------------------------------------------------------
// Launch
// ---------------------------------------------------------------------------
extern "C" void kernel_launch(void* const* d_in, const int* in_sizes, int n_in,
                              void* d_out, int out_size) {
    const float* x      = (const float*)d_in[0];
    const int*   binary = (const int*)  d_in[1];
    const float* scale  = (const float*)d_in[2];
    const float* bias   = (const float*)d_in[3];
    float*       out    = (float*)d_out;

    fused_kernel<<<GRID_F, 256>>>(binary, scale, x, bias, out);
}